// round 8
// baseline (speedup 1.0000x reference)
#include <cuda_runtime.h>

#define B_TOTAL 1024
#define N 128
#define MW 1.0f
#define NITERS 300

typedef unsigned long long u64;

// ---------- packed f32x2 helpers (Blackwell) ----------
__device__ __forceinline__ u64 pack2(float lo, float hi) {
    u64 r; asm("mov.b64 %0, {%1, %2};" : "=l"(r) : "f"(lo), "f"(hi)); return r;
}
__device__ __forceinline__ void unpack2(u64 p, float& lo, float& hi) {
    asm("mov.b64 {%0, %1}, %2;" : "=f"(lo), "=f"(hi) : "l"(p));
}
__device__ __forceinline__ void ffma2(u64& d, u64 a, u64 b) {
    asm("fma.rn.f32x2 %0, %1, %2, %3;" : "=l"(d) : "l"(a), "l"(b), "l"(d));
}
__device__ __forceinline__ u64 fmul2(u64 a, u64 b) {
    u64 r; asm("mul.rn.f32x2 %0, %1, %2;" : "=l"(r) : "l"(a), "l"(b)); return r;
}

__device__ __forceinline__ float wsum(float v) {
#pragma unroll
    for (int m = 16; m >= 1; m >>= 1)
        v += __shfl_xor_sync(0xffffffffu, v, m);
    return v;
}

// s(tau) = sum saturate(v - tau); c = #{0 < v-tau < 1}
__device__ __forceinline__ void eval_sc(float4 vv, float tau, float& s, float& c) {
    const float z0 = __saturatef(vv.x - tau);
    const float z1 = __saturatef(vv.y - tau);
    const float z2 = __saturatef(vv.z - tau);
    const float z3 = __saturatef(vv.w - tau);
    s = (z0 + z1) + (z2 + z3);
    c = ((z0 > 0.f && z0 < 1.f) ? 1.f : 0.f)
      + ((z1 > 0.f && z1 < 1.f) ? 1.f : 0.f)
      + ((z2 > 0.f && z2 < 1.f) ? 1.f : 0.f)
      + ((z3 > 0.f && z3 < 1.f) ? 1.f : 0.f);
}

__global__ __launch_bounds__(128, 3)
void markowitz_kernel(const float* __restrict__ rets,
                      const float* __restrict__ cov,
                      const float* __restrict__ gamma_sqrt,
                      const float* __restrict__ alpha,
                      float* __restrict__ out)
{
    __shared__ __align__(16) float ysh[N];
    __shared__ __align__(16) float vsh[N];
    __shared__ float red[4];

    const int b = blockIdx.x;
    const int i = threadIdx.x;
    const int lane = i & 31;

    const float* __restrict__ Cb = cov + (size_t)b * (N * N);

    // ---------------- Phase A: Q = g^2 * C^T C + |alpha| I (packed pairs) ----------------
    u64 qp[N / 2];
#pragma unroll
    for (int j = 0; j < N / 2; ++j) qp[j] = 0ULL;

#pragma unroll 1
    for (int k = 0; k < N; ++k) {
        const float c = Cb[k * N + i];                               // coalesced
        const u64 c2 = pack2(c, c);
        const ulonglong2* __restrict__ rk = (const ulonglong2*)(Cb + k * N);  // broadcast
#pragma unroll
        for (int j4 = 0; j4 < N / 4; ++j4) {
            ulonglong2 r = rk[j4];
            ffma2(qp[2 * j4 + 0], c2, r.x);
            ffma2(qp[2 * j4 + 1], c2, r.y);
        }
    }

    const float g = gamma_sqrt[b];
    const float g2 = g * g;
    const float aab = fabsf(alpha[b]);

    const u64 g22 = pack2(g2, g2);
#pragma unroll
    for (int j = 0; j < N / 2; ++j) qp[j] = fmul2(qp[j], g22);
    {   // diagonal: q[i] += |alpha|
        float e0, e1; unpack2(qp[i >> 1], e0, e1);
        if (i & 1) e1 += aab; else e0 += aab;
        qp[i >> 1] = pack2(e0, e1);
    }

    // Frobenius norm -> step = 1/(2*||Q||_F)
    u64 f2 = 0ULL;
#pragma unroll
    for (int j = 0; j < N / 2; ++j) ffma2(f2, qp[j], qp[j]);
    float fa, fb; unpack2(f2, fa, fb);
    float fro = wsum(fa + fb);
    if (lane == 0) red[i >> 5] = fro;
    __syncthreads();
    const float totF = (red[0] + red[1]) + (red[2] + red[3]);
    const float step = 1.0f / (2.0f * sqrtf(totF));

    // Fold: qs = 2*step*Q, rs = step*rets
    const float two_step = 2.0f * step;
    const u64 ts2 = pack2(two_step, two_step);
#pragma unroll
    for (int j = 0; j < N / 2; ++j) qp[j] = fmul2(qp[j], ts2);
    const float rs = step * rets[(size_t)b * N + i];

    // ---------------- Phase B: FISTA ----------------
    float w = 1.0f / (float)N;
    float y = w;
    float t = 1.0f;
    float tau_prev = 0.0f;
    ysh[i] = y;
    __syncthreads();

#pragma unroll 1
    for (int it = 0; it < NITERS; ++it) {
        // grad step: v = y - (2*step*Q) y + step*rets  (packed matvec)
        const ulonglong2* __restrict__ yv = (const ulonglong2*)ysh;
        u64 d0 = 0ULL, d1 = 0ULL, d2 = 0ULL, d3 = 0ULL;
#pragma unroll
        for (int j4 = 0; j4 < N / 4; j4 += 2) {
            ulonglong2 u0 = yv[j4];
            ulonglong2 u1 = yv[j4 + 1];
            ffma2(d0, qp[2 * j4 + 0], u0.x);
            ffma2(d1, qp[2 * j4 + 1], u0.y);
            ffma2(d2, qp[2 * j4 + 2], u1.x);
            ffma2(d3, qp[2 * j4 + 3], u1.y);
        }
        float p0, p1, p2, p3, p4, p5, p6, p7;
        unpack2(d0, p0, p1); unpack2(d1, p2, p3);
        unpack2(d2, p4, p5); unpack2(d3, p6, p7);
        const float v = y - (((p0 + p1) + (p2 + p3)) + ((p4 + p5) + (p6 + p7))) + rs;
        vsh[i] = v;
        __syncthreads();

        // -------- warp-redundant projection: fixed 4-eval safeguarded Newton --------
        const float4 vv = ((const float4*)vsh)[lane];

        // Eval 1 at tau_prev (bracket-independent) fused with minmax butterflies
        float tau = tau_prev;
        float s, c;
        eval_sc(vv, tau, s, c);
        float mn = fminf(fminf(vv.x, vv.y), fminf(vv.z, vv.w));
        float mx = fmaxf(fmaxf(vv.x, vv.y), fmaxf(vv.z, vv.w));
#pragma unroll
        for (int m = 16; m >= 1; m >>= 1) {
            s  += __shfl_xor_sync(0xffffffffu, s, m);
            c  += __shfl_xor_sync(0xffffffffu, c, m);
            mn = fminf(mn, __shfl_xor_sync(0xffffffffu, mn, m));
            mx = fmaxf(mx, __shfl_xor_sync(0xffffffffu, mx, m));
        }
        float lo = mn - MW;
        float hi = mx;
        if (s > 1.0f) lo = fmaxf(lo, tau); else hi = fminf(hi, tau);
        {
            const float nt = tau + (s - 1.0f) / fmaxf(c, 1.0f);
            tau = (nt >= lo && nt <= hi) ? nt : 0.5f * (lo + hi);
        }

        // Evals 2,3: Newton + bracket safeguard (branch-free, unrolled)
#pragma unroll
        for (int r = 0; r < 2; ++r) {
            eval_sc(vv, tau, s, c);
#pragma unroll
            for (int m = 16; m >= 1; m >>= 1) {
                s += __shfl_xor_sync(0xffffffffu, s, m);
                c += __shfl_xor_sync(0xffffffffu, c, m);
            }
            if (s > 1.0f) lo = tau; else hi = tau;
            const float nt = tau + (s - 1.0f) / fmaxf(c, 1.0f);
            tau = (nt >= lo && nt <= hi) ? nt : 0.5f * (lo + hi);
        }

        // Eval 4 (final): s,c at tau give the reference's active-set tau via
        // the Newton identity: tau_d = tau + (s-1)/nfree
        eval_sc(vv, tau, s, c);
#pragma unroll
        for (int m = 16; m >= 1; m >>= 1) {
            s += __shfl_xor_sync(0xffffffffu, s, m);
            c += __shfl_xor_sync(0xffffffffu, c, m);
        }
        const float nfree = fmaxf(c, 1.0f);
        const float tau_d = tau + (s - 1.0f) / nfree;
        tau_prev = tau_d;     // warm start next iteration at the root

        // own-element update (classify against last eval point tau)
        const float z = v - tau;
        const bool fr = (z > 0.0f) && (z < MW);
        const bool up = (z >= MW);
        const float wn = fr ? (v - tau_d) : (up ? MW : 0.0f);

        const float tn = 0.5f * (1.0f + sqrtf(1.0f + 4.0f * t * t));
        const float yn = wn + ((t - 1.0f) / tn) * (wn - w);
        w = wn;
        y = yn;
        t = tn;

        ysh[i] = yn;          // safe: vsh barrier ordered all matvec reads
        __syncthreads();
    }

    out[(size_t)b * N + i] = w;
}

extern "C" void kernel_launch(void* const* d_in, const int* in_sizes, int n_in,
                              void* d_out, int out_size) {
    const float* rets  = (const float*)d_in[0];
    const float* cov   = (const float*)d_in[1];
    const float* gamma = (const float*)d_in[2];
    const float* alpha = (const float*)d_in[3];
    float* out = (float*)d_out;
    (void)in_sizes; (void)n_in; (void)out_size;

    markowitz_kernel<<<B_TOTAL, N>>>(rets, cov, gamma, alpha, out);
}

// round 10
// speedup vs baseline: 1.3219x; 1.3219x over previous
#include <cuda_runtime.h>

#define B_TOTAL 1024
#define N 128
#define MW 1.0f
#define NITERS 300
#define MAX_EVALS 24

typedef unsigned long long u64;

// ---------- packed f32x2 helpers (Blackwell) ----------
__device__ __forceinline__ u64 pack2(float lo, float hi) {
    u64 r; asm("mov.b64 %0, {%1, %2};" : "=l"(r) : "f"(lo), "f"(hi)); return r;
}
__device__ __forceinline__ void unpack2(u64 p, float& lo, float& hi) {
    asm("mov.b64 {%0, %1}, %2;" : "=f"(lo), "=f"(hi) : "l"(p));
}
__device__ __forceinline__ void ffma2(u64& d, u64 a, u64 b) {
    asm("fma.rn.f32x2 %0, %1, %2, %3;" : "=l"(d) : "l"(a), "l"(b), "l"(d));
}
__device__ __forceinline__ u64 fmul2(u64 a, u64 b) {
    u64 r; asm("mul.rn.f32x2 %0, %1, %2;" : "=l"(r) : "l"(a), "l"(b)); return r;
}

__device__ __forceinline__ float wsum(float v) {
#pragma unroll
    for (int m = 16; m >= 1; m >>= 1)
        v += __shfl_xor_sync(0xffffffffu, v, m);
    return v;
}

// s(tau) = sum saturate(v - tau); c = #{0 < v-tau < 1}
__device__ __forceinline__ void eval_sc(float4 vv, float tau, float& s, float& c) {
    const float z0 = __saturatef(vv.x - tau);
    const float z1 = __saturatef(vv.y - tau);
    const float z2 = __saturatef(vv.z - tau);
    const float z3 = __saturatef(vv.w - tau);
    s = (z0 + z1) + (z2 + z3);
    c = ((z0 > 0.f && z0 < 1.f) ? 1.f : 0.f)
      + ((z1 > 0.f && z1 < 1.f) ? 1.f : 0.f)
      + ((z2 > 0.f && z2 < 1.f) ? 1.f : 0.f)
      + ((z3 > 0.f && z3 < 1.f) ? 1.f : 0.f);
}

__global__ __launch_bounds__(128, 3)
void markowitz_kernel(const float* __restrict__ rets,
                      const float* __restrict__ cov,
                      const float* __restrict__ gamma_sqrt,
                      const float* __restrict__ alpha,
                      float* __restrict__ out)
{
    __shared__ __align__(16) float ysh[N];
    __shared__ __align__(16) float vsh[N];
    __shared__ float red[4];
    __shared__ float tau_sh[2];   // {tau_last_eval, tau_d}

    const int b = blockIdx.x;
    const int i = threadIdx.x;
    const int lane = i & 31;

    const float* __restrict__ Cb = cov + (size_t)b * (N * N);

    // ---------------- Phase A: Q = g^2 * C^T C + |alpha| I (packed pairs) ----------------
    u64 qp[N / 2];
#pragma unroll
    for (int j = 0; j < N / 2; ++j) qp[j] = 0ULL;

#pragma unroll 1
    for (int k = 0; k < N; ++k) {
        const float c = Cb[k * N + i];                               // coalesced
        const u64 c2 = pack2(c, c);
        const ulonglong2* __restrict__ rk = (const ulonglong2*)(Cb + k * N);  // broadcast
#pragma unroll
        for (int j4 = 0; j4 < N / 4; ++j4) {
            ulonglong2 r = rk[j4];
            ffma2(qp[2 * j4 + 0], c2, r.x);
            ffma2(qp[2 * j4 + 1], c2, r.y);
        }
    }

    const float g = gamma_sqrt[b];
    const float g2 = g * g;
    const float aab = fabsf(alpha[b]);

    const u64 g22 = pack2(g2, g2);
#pragma unroll
    for (int j = 0; j < N / 2; ++j) qp[j] = fmul2(qp[j], g22);
    {   // diagonal: q[i] += |alpha|
        float e0, e1; unpack2(qp[i >> 1], e0, e1);
        if (i & 1) e1 += aab; else e0 += aab;
        qp[i >> 1] = pack2(e0, e1);
    }

    // Frobenius norm -> step = 1/(2*||Q||_F)
    u64 f2 = 0ULL;
#pragma unroll
    for (int j = 0; j < N / 2; ++j) ffma2(f2, qp[j], qp[j]);
    float fa, fb; unpack2(f2, fa, fb);
    float fro = wsum(fa + fb);
    if (lane == 0) red[i >> 5] = fro;
    __syncthreads();
    const float totF = (red[0] + red[1]) + (red[2] + red[3]);
    const float step = 1.0f / (2.0f * sqrtf(totF));

    // Fold: qs = 2*step*Q, rs = step*rets
    const float two_step = 2.0f * step;
    const u64 ts2 = pack2(two_step, two_step);
#pragma unroll
    for (int j = 0; j < N / 2; ++j) qp[j] = fmul2(qp[j], ts2);
    const float rs = step * rets[(size_t)b * N + i];

    // ---------------- Phase B: FISTA ----------------
    float w = 1.0f / (float)N;
    float y = w;
    float t = 1.0f;
    float tau_prev = 0.0f;   // meaningful in warp 0 only
    ysh[i] = y;
    __syncthreads();

#pragma unroll 1
    for (int it = 0; it < NITERS; ++it) {
        // grad step: v = y - (2*step*Q) y + step*rets  (packed matvec)
        const ulonglong2* __restrict__ yv = (const ulonglong2*)ysh;
        u64 d0 = 0ULL, d1 = 0ULL, d2 = 0ULL, d3 = 0ULL;
#pragma unroll
        for (int j4 = 0; j4 < N / 4; j4 += 2) {
            ulonglong2 u0 = yv[j4];
            ulonglong2 u1 = yv[j4 + 1];
            ffma2(d0, qp[2 * j4 + 0], u0.x);
            ffma2(d1, qp[2 * j4 + 1], u0.y);
            ffma2(d2, qp[2 * j4 + 2], u1.x);
            ffma2(d3, qp[2 * j4 + 3], u1.y);
        }
        float p0, p1, p2, p3, p4, p5, p6, p7;
        unpack2(d0, p0, p1); unpack2(d1, p2, p3);
        unpack2(d2, p4, p5); unpack2(d3, p6, p7);
        const float v = y - (((p0 + p1) + (p2 + p3)) + ((p4 + p5) + (p6 + p7))) + rs;
        vsh[i] = v;
        __syncthreads();

        // -------- projection on warp 0 only (adaptive, warm-started Newton) --------
        if (i < 32) {
            const float4 vv = ((const float4*)vsh)[lane];

            // Eval 1 at tau_prev fused with minmax butterflies
            float tau = tau_prev;
            float s, c;
            eval_sc(vv, tau, s, c);
            float mn = fminf(fminf(vv.x, vv.y), fminf(vv.z, vv.w));
            float mx = fmaxf(fmaxf(vv.x, vv.y), fmaxf(vv.z, vv.w));
#pragma unroll
            for (int m = 16; m >= 1; m >>= 1) {
                s  += __shfl_xor_sync(0xffffffffu, s, m);
                c  += __shfl_xor_sync(0xffffffffu, c, m);
                mn = fminf(mn, __shfl_xor_sync(0xffffffffu, mn, m));
                mx = fmaxf(mx, __shfl_xor_sync(0xffffffffu, mx, m));
            }
            float lo = mn - MW;
            float hi = mx;
            const float eps = 1e-6f * (hi - lo);
            if (s > 1.0f) lo = fmaxf(lo, tau); else hi = fminf(hi, tau);

            if (s != 1.0f) {
                {
                    const float nt = tau + (s - 1.0f) / fmaxf(c, 1.0f);
                    tau = (nt > lo && nt < hi) ? nt : 0.5f * (lo + hi);
                }
#pragma unroll 1
                for (int e = 0; e < MAX_EVALS; ++e) {
                    eval_sc(vv, tau, s, c);
#pragma unroll
                    for (int m = 16; m >= 1; m >>= 1) {
                        s += __shfl_xor_sync(0xffffffffu, s, m);
                        c += __shfl_xor_sync(0xffffffffu, c, m);
                    }
                    if (s > 1.0f) lo = tau; else hi = tau;
                    if (s == 1.0f) break;
                    if (hi - lo <= eps) break;
                    const float nt = tau + (s - 1.0f) / fmaxf(c, 1.0f);
                    tau = (nt > lo && nt < hi) ? nt : 0.5f * (lo + hi);
                }
            }

            // Newton identity == reference's active-set re-derived tau
            const float nfree = fmaxf(c, 1.0f);
            const float tau_d = tau + (s - 1.0f) / nfree;
            tau_prev = tau_d;                 // warm start next iteration

            if (lane == 0) { tau_sh[0] = tau; tau_sh[1] = tau_d; }
        }
        __syncthreads();

        const float tauc = tau_sh[0];
        const float tau_d = tau_sh[1];

        // own-element update (classify against last eval point)
        const float z = v - tauc;
        const bool fr = (z > 0.0f) && (z < MW);
        const bool up = (z >= MW);
        const float wn = fr ? (v - tau_d) : (up ? MW : 0.0f);

        const float tn = 0.5f * (1.0f + sqrtf(1.0f + 4.0f * t * t));
        const float yn = wn + ((t - 1.0f) / tn) * (wn - w);
        w = wn;
        y = yn;
        t = tn;

        ysh[i] = yn;
        __syncthreads();
    }

    out[(size_t)b * N + i] = w;
}

extern "C" void kernel_launch(void* const* d_in, const int* in_sizes, int n_in,
                              void* d_out, int out_size) {
    const float* rets  = (const float*)d_in[0];
    const float* cov   = (const float*)d_in[1];
    const float* gamma = (const float*)d_in[2];
    const float* alpha = (const float*)d_in[3];
    float* out = (float*)d_out;
    (void)in_sizes; (void)n_in; (void)out_size;

    markowitz_kernel<<<B_TOTAL, N>>>(rets, cov, gamma, alpha, out);
}

// round 11
// speedup vs baseline: 1.4063x; 1.0639x over previous
#include <cuda_runtime.h>

#define B_TOTAL 1024
#define N 128
#define MW 1.0f
#define NITERS 300
#define MAX_EVALS 16
#define FIX_ONE 16777216u          // 2^24
#define FIX_SCALE 16777216.0f
#define FIX_INV (1.0f / 16777216.0f)

typedef unsigned long long u64;
typedef unsigned int u32;

// ---------- packed f32x2 helpers (Blackwell) ----------
__device__ __forceinline__ u64 pack2(float lo, float hi) {
    u64 r; asm("mov.b64 %0, {%1, %2};" : "=l"(r) : "f"(lo), "f"(hi)); return r;
}
__device__ __forceinline__ void unpack2(u64 p, float& lo, float& hi) {
    asm("mov.b64 {%0, %1}, %2;" : "=f"(lo), "=f"(hi) : "l"(p));
}
__device__ __forceinline__ void ffma2(u64& d, u64 a, u64 b) {
    asm("fma.rn.f32x2 %0, %1, %2, %3;" : "=l"(d) : "l"(a), "l"(b), "l"(d));
}
__device__ __forceinline__ u64 fmul2(u64 a, u64 b) {
    u64 r; asm("mul.rn.f32x2 %0, %1, %2;" : "=l"(r) : "l"(a), "l"(b)); return r;
}

// ---------- single-stage warp reductions (sm_80+ integer redux) ----------
__device__ __forceinline__ u32 redux_add(u32 v) {
    u32 r; asm("redux.sync.add.u32 %0, %1, 0xffffffff;" : "=r"(r) : "r"(v)); return r;
}
__device__ __forceinline__ u32 redux_min(u32 v) {
    u32 r; asm("redux.sync.min.u32 %0, %1, 0xffffffff;" : "=r"(r) : "r"(v)); return r;
}
__device__ __forceinline__ u32 redux_max(u32 v) {
    u32 r; asm("redux.sync.max.u32 %0, %1, 0xffffffff;" : "=r"(r) : "r"(v)); return r;
}

// monotone float <-> orderable u32 key
__device__ __forceinline__ u32 fkey(float x) {
    u32 u = __float_as_uint(x);
    return (u & 0x80000000u) ? ~u : (u | 0x80000000u);
}
__device__ __forceinline__ float funkey(u32 k) {
    u32 u = (k & 0x80000000u) ? (k & 0x7FFFFFFFu) : ~k;
    return __uint_as_float(u);
}

__device__ __forceinline__ float wsum(float v) {
#pragma unroll
    for (int m = 16; m >= 1; m >>= 1)
        v += __shfl_xor_sync(0xffffffffu, v, m);
    return v;
}

// Fixed-point eval: S = round(2^24 * sum saturate(v-tau)); C = #{0 < z < 1}
__device__ __forceinline__ void eval_int(float4 vv, float tau, u32& S, u32& C) {
    const float z0 = __saturatef(vv.x - tau);
    const float z1 = __saturatef(vv.y - tau);
    const float z2 = __saturatef(vv.z - tau);
    const float z3 = __saturatef(vv.w - tau);
    const u32 a0 = __float2uint_rn(z0 * FIX_SCALE);
    const u32 a1 = __float2uint_rn(z1 * FIX_SCALE);
    const u32 a2 = __float2uint_rn(z2 * FIX_SCALE);
    const u32 a3 = __float2uint_rn(z3 * FIX_SCALE);
    u32 s = (a0 + a1) + (a2 + a3);
    u32 c = (u32)(a0 > 0u && a0 < FIX_ONE)
          + (u32)(a1 > 0u && a1 < FIX_ONE)
          + (u32)(a2 > 0u && a2 < FIX_ONE)
          + (u32)(a3 > 0u && a3 < FIX_ONE);
    S = redux_add(s);
    C = redux_add(c);
}

__device__ __forceinline__ float newton_from(float tau, u32 S, u32 C) {
    const float ds = (float)(int)(S - FIX_ONE);          // (s-1) * 2^24
    const float cf = fmaxf((float)C, 1.0f);
    return tau + ds * FIX_INV / cf;
}

__global__ __launch_bounds__(128, 3)
void markowitz_kernel(const float* __restrict__ rets,
                      const float* __restrict__ cov,
                      const float* __restrict__ gamma_sqrt,
                      const float* __restrict__ alpha,
                      float* __restrict__ out)
{
    __shared__ __align__(16) float ysh[N];
    __shared__ __align__(16) float vsh[N];
    __shared__ float red[4];
    __shared__ float tau_sh[2];   // {tau_last_eval, tau_d}

    const int b = blockIdx.x;
    const int i = threadIdx.x;
    const int lane = i & 31;

    const float* __restrict__ Cb = cov + (size_t)b * (N * N);

    // ---------------- Phase A: Q = g^2 * C^T C + |alpha| I (packed pairs) ----------------
    u64 qp[N / 2];
#pragma unroll
    for (int j = 0; j < N / 2; ++j) qp[j] = 0ULL;

#pragma unroll 1
    for (int k = 0; k < N; ++k) {
        const float c = Cb[k * N + i];                               // coalesced
        const u64 c2 = pack2(c, c);
        const ulonglong2* __restrict__ rk = (const ulonglong2*)(Cb + k * N);  // broadcast
#pragma unroll
        for (int j4 = 0; j4 < N / 4; ++j4) {
            ulonglong2 r = rk[j4];
            ffma2(qp[2 * j4 + 0], c2, r.x);
            ffma2(qp[2 * j4 + 1], c2, r.y);
        }
    }

    const float g = gamma_sqrt[b];
    const float g2 = g * g;
    const float aab = fabsf(alpha[b]);

    const u64 g22 = pack2(g2, g2);
#pragma unroll
    for (int j = 0; j < N / 2; ++j) qp[j] = fmul2(qp[j], g22);
    {   // diagonal: q[i] += |alpha|
        float e0, e1; unpack2(qp[i >> 1], e0, e1);
        if (i & 1) e1 += aab; else e0 += aab;
        qp[i >> 1] = pack2(e0, e1);
    }

    // Frobenius norm -> step = 1/(2*||Q||_F)
    u64 f2 = 0ULL;
#pragma unroll
    for (int j = 0; j < N / 2; ++j) ffma2(f2, qp[j], qp[j]);
    float fa, fb; unpack2(f2, fa, fb);
    float fro = wsum(fa + fb);
    if (lane == 0) red[i >> 5] = fro;
    __syncthreads();
    const float totF = (red[0] + red[1]) + (red[2] + red[3]);
    const float step = 1.0f / (2.0f * sqrtf(totF));

    // Fold: qs = 2*step*Q, rs = step*rets
    const float two_step = 2.0f * step;
    const u64 ts2 = pack2(two_step, two_step);
#pragma unroll
    for (int j = 0; j < N / 2; ++j) qp[j] = fmul2(qp[j], ts2);
    const float rs = step * rets[(size_t)b * N + i];

    // ---------------- Phase B: FISTA ----------------
    float w = 1.0f / (float)N;
    float y = w;
    float t = 1.0f;
    float tau_prev = 0.0f;   // meaningful in warp 0 only
    ysh[i] = y;
    __syncthreads();

#pragma unroll 1
    for (int it = 0; it < NITERS; ++it) {
        // grad step: v = y - (2*step*Q) y + step*rets  (packed matvec)
        const ulonglong2* __restrict__ yv = (const ulonglong2*)ysh;
        u64 d0 = 0ULL, d1 = 0ULL, d2 = 0ULL, d3 = 0ULL;
#pragma unroll
        for (int j4 = 0; j4 < N / 4; j4 += 2) {
            ulonglong2 u0 = yv[j4];
            ulonglong2 u1 = yv[j4 + 1];
            ffma2(d0, qp[2 * j4 + 0], u0.x);
            ffma2(d1, qp[2 * j4 + 1], u0.y);
            ffma2(d2, qp[2 * j4 + 2], u1.x);
            ffma2(d3, qp[2 * j4 + 3], u1.y);
        }
        float p0, p1, p2, p3, p4, p5, p6, p7;
        unpack2(d0, p0, p1); unpack2(d1, p2, p3);
        unpack2(d2, p4, p5); unpack2(d3, p6, p7);
        const float v = y - (((p0 + p1) + (p2 + p3)) + ((p4 + p5) + (p6 + p7))) + rs;
        vsh[i] = v;
        __syncthreads();

        // -------- projection on warp 0: Newton w/ single-stage integer redux --------
        if (i < 32) {
            const float4 vv = ((const float4*)vsh)[lane];

            // bracket minmax (single-stage) runs in parallel with eval 1
            const float lmn = fminf(fminf(vv.x, vv.y), fminf(vv.z, vv.w));
            const float lmx = fmaxf(fmaxf(vv.x, vv.y), fmaxf(vv.z, vv.w));
            const u32 kmn = redux_min(fkey(lmn));
            const u32 kmx = redux_max(fkey(lmx));

            float tau = tau_prev;
            u32 S, C;
            eval_int(vv, tau, S, C);

            float lo = funkey(kmn) - MW;
            float hi = funkey(kmx);
            const float eps = 1e-6f * (hi - lo);
            if (S > FIX_ONE) lo = fmaxf(lo, tau); else hi = fminf(hi, tau);

            if (S != FIX_ONE) {
                {
                    const float nt = newton_from(tau, S, C);
                    tau = (nt > lo && nt < hi) ? nt : 0.5f * (lo + hi);
                }
#pragma unroll 1
                for (int e = 0; e < MAX_EVALS; ++e) {
                    eval_int(vv, tau, S, C);
                    if (S > FIX_ONE) lo = tau; else hi = tau;
                    if (S == FIX_ONE) break;
                    if (hi - lo <= eps) break;
                    const float nt = newton_from(tau, S, C);
                    tau = (nt > lo && nt < hi) ? nt : 0.5f * (lo + hi);
                }
            }

            // Newton identity == reference's active-set re-derived tau
            const float tau_d = newton_from(tau, S, C);
            tau_prev = tau_d;                 // warm start next iteration

            if (lane == 0) { tau_sh[0] = tau; tau_sh[1] = tau_d; }
        }
        __syncthreads();

        const float tauc = tau_sh[0];
        const float tau_d = tau_sh[1];

        // own-element update (classify against last eval point)
        const float z = v - tauc;
        const bool fr = (z > 0.0f) && (z < MW);
        const bool up = (z >= MW);
        const float wn = fr ? (v - tau_d) : (up ? MW : 0.0f);

        const float tn = 0.5f * (1.0f + sqrtf(1.0f + 4.0f * t * t));
        const float yn = wn + ((t - 1.0f) / tn) * (wn - w);
        w = wn;
        y = yn;
        t = tn;

        ysh[i] = yn;
        __syncthreads();
    }

    out[(size_t)b * N + i] = w;
}

extern "C" void kernel_launch(void* const* d_in, const int* in_sizes, int n_in,
                              void* d_out, int out_size) {
    const float* rets  = (const float*)d_in[0];
    const float* cov   = (const float*)d_in[1];
    const float* gamma = (const float*)d_in[2];
    const float* alpha = (const float*)d_in[3];
    float* out = (float*)d_out;
    (void)in_sizes; (void)n_in; (void)out_size;

    markowitz_kernel<<<B_TOTAL, N>>>(rets, cov, gamma, alpha, out);
}